// round 5
// baseline (speedup 1.0000x reference)
#include <cuda_runtime.h>
#include <math.h>
#include <stdint.h>

#define T_STEPS 2048
#define BATCH   64
#define HID     256
#define GATE4   1024
#define NG      (BATCH*HID)          /* 16384 */
#define REC_THREADS 512
#define GST     5                    /* gates_sm row stride (floats) */

typedef unsigned long long u64;

/* Scratch (device globals: no allocation allowed in kernel_launch) */
__device__ float g_xg[134217728];    /* [T][B][4H] precomputed input gates */

/* ---- packed f32x2 helpers ---- */
__device__ __forceinline__ u64 ffma2(u64 a, u64 b, u64 c){
  u64 d; asm("fma.rn.f32x2 %0, %1, %2, %3;" : "=l"(d) : "l"(a), "l"(b), "l"(c));
  return d;
}
__device__ __forceinline__ u64 fmul2(u64 a, u64 b){
  u64 d; asm("mul.rn.f32x2 %0, %1, %2;" : "=l"(d) : "l"(a), "l"(b));
  return d;
}
__device__ __forceinline__ u64 fadd2(u64 a, u64 b){
  u64 d; asm("add.rn.f32x2 %0, %1, %2;" : "=l"(d) : "l"(a), "l"(b));
  return d;
}
__device__ __forceinline__ float hadd2(u64 a){
  unsigned lo, hi;
  asm("mov.b64 {%0, %1}, %2;" : "=r"(lo), "=r"(hi) : "l"(a));
  return __uint_as_float(lo) + __uint_as_float(hi);
}

__device__ __forceinline__ float fsigm(float x){
  return __fdividef(1.f, 1.f + __expf(-x));
}
__device__ __forceinline__ float ftanh(float x){
  return __fdividef(2.f, 1.f + __expf(-2.f*x)) - 1.f;
}

/* ---- cluster / DSMEM helpers ---- */
__device__ __forceinline__ uint32_t smem_u32(const void* p){
  uint32_t a;
  asm("{ .reg .u64 t; cvta.to.shared.u64 t, %1; cvt.u32.u64 %0, t; }"
      : "=r"(a) : "l"(p));
  return a;
}
__device__ __forceinline__ uint32_t mapa_rank(uint32_t addr, uint32_t rk){
  uint32_t r;
  asm("mapa.shared::cluster.u32 %0, %1, %2;" : "=r"(r) : "r"(addr), "r"(rk));
  return r;
}
__device__ __forceinline__ void st_cluster_f32(uint32_t addr, float v){
  asm volatile("st.shared::cluster.f32 [%0], %1;" :: "r"(addr), "f"(v) : "memory");
}
__device__ __forceinline__ uint32_t ctarank(){
  uint32_t r; asm("mov.u32 %0, %%cluster_ctarank;" : "=r"(r)); return r;
}

/* ---------------- Kernel A: x_gates = input @ W_ih^T + b_ih + b_hh ----------------
 * Reverted to the Round-3 plain-FFMA version (measured ~2.0ms; the FFMA2
 * variant regressed ~+1.2ms from u64 tile staging overhead). */
__global__ void __launch_bounds__(256, 2) xgates_gemm(
    const float* __restrict__ A, const float* __restrict__ W,
    const float* __restrict__ bih, const float* __restrict__ bhh)
{
  __shared__ float a_t[16][132];
  __shared__ float b_t[16][68];
  const int tid = threadIdx.x;
  const int bx = blockIdx.x, by = blockIdx.y;
  const int tx = tid & 15, ty = tid >> 4;

  float acc[8][4];
  #pragma unroll
  for (int m=0;m<8;m++)
    #pragma unroll
    for (int n=0;n<4;n++) acc[m][n]=0.f;

  const float* Ab = A + (size_t)by*128*256;
  const float* Wb = W + (size_t)bx*64*256;

  for (int kt=0; kt<16; ++kt){
    const int k0 = kt*16;
    #pragma unroll
    for (int r=0;r<2;r++){
      int idx = tid + r*256;
      int row = idx >> 2, kq = idx & 3;
      float4 v = *(const float4*)(Ab + (size_t)row*256 + k0 + kq*4);
      a_t[kq*4+0][row]=v.x; a_t[kq*4+1][row]=v.y;
      a_t[kq*4+2][row]=v.z; a_t[kq*4+3][row]=v.w;
    }
    {
      int n = tid >> 2, kq = tid & 3;
      float4 v = *(const float4*)(Wb + (size_t)n*256 + k0 + kq*4);
      b_t[kq*4+0][n]=v.x; b_t[kq*4+1][n]=v.y;
      b_t[kq*4+2][n]=v.z; b_t[kq*4+3][n]=v.w;
    }
    __syncthreads();
    #pragma unroll
    for (int k=0;k<16;k++){
      float af[8], bf[4];
      *(float4*)(af)   = *(const float4*)&a_t[k][ty*8];
      *(float4*)(af+4) = *(const float4*)&a_t[k][ty*8+4];
      *(float4*)(bf)   = *(const float4*)&b_t[k][tx*4];
      #pragma unroll
      for (int m=0;m<8;m++)
        #pragma unroll
        for (int n=0;n<4;n++)
          acc[m][n] += af[m]*bf[n];
    }
    __syncthreads();
  }

  const int gn = bx*64 + tx*4;
  const float bb0 = bih[gn+0]+bhh[gn+0];
  const float bb1 = bih[gn+1]+bhh[gn+1];
  const float bb2 = bih[gn+2]+bhh[gn+2];
  const float bb3 = bih[gn+3]+bhh[gn+3];
  #pragma unroll
  for (int m=0;m<8;m++){
    int gm = by*128 + ty*8 + m;
    float4 o = make_float4(acc[m][0]+bb0, acc[m][1]+bb1, acc[m][2]+bb2, acc[m][3]+bb3);
    *(float4*)(g_xg + (size_t)gm*GATE4 + gn) = o;
  }
}

/* ---------------- Kernel B: cluster-chained recurrence ----------------
 * 16 chains x 8-CTA clusters = 128 blocks. Chain owns 4 batches, cluster-CTA
 * rank r owns j in [32r, 32r+32) for all 4 gates (128 gate-rows, W slice in
 * registers: 64 floats/lane, no duplication). h lives ONLY in smem: each
 * CTA's epilogue stores its 128 new h values into all 8 cluster CTAs' smem
 * via st.shared::cluster; one barrier.cluster per step. Chains are fully
 * independent -> no global synchronization, no reset state.
 * Thread layout: warp wid owns rows wid*8..wid*8+7; lane = (lg: 16-way
 * k-split, rh: row-half). Per step/thread: 16 LDS.128 + 128 FFMA2 +
 * 32 SHFL; epilogue on tid<128 (b = tid>>5, jl = tid&31). */
__global__ void __launch_bounds__(REC_THREADS, 1) __cluster_dims__(8, 1, 1)
lstm_rec(const float* __restrict__ h0, const float* __restrict__ c0,
         const float* __restrict__ W_hh, float* __restrict__ out)
{
  __shared__ float h_buf[2][4][256];     /* [buf][local batch][j] : 8 KB */
  __shared__ float gates_sm[128*GST];    /* [gate-row rl][b], rl = g*32+jl */

  const int tid  = threadIdx.x;
  const uint32_t rank = ctarank();
  const int chain = blockIdx.x >> 3;
  const int b0   = chain*4;
  const int j0   = (int)rank*32;

  const int wid  = tid >> 5, lane = tid & 31;
  const int lg   = lane & 15, rh = lane >> 4;

  /* W_hh slice -> registers. rl in [0,128): gate = rl>>5, j = j0 + (rl&31). */
  ulonglong2 wr2[4][4];
  #pragma unroll
  for (int r=0;r<4;r++){
    const int rl = wid*8 + rh*4 + r;
    const int grow = (rl>>5)*HID + j0 + (rl&31);
    #pragma unroll
    for (int q=0;q<4;q++)
      wr2[r][q] = *(const ulonglong2*)(W_hh + (size_t)grow*HID + lg*4 + 64*q);
  }

  /* peer smem base addresses (h_buf) for all 8 cluster CTAs */
  const uint32_t hbase = smem_u32(h_buf);
  uint32_t peer[8];
  #pragma unroll
  for (int rk=0; rk<8; rk++) peer[rk] = mapa_rank(hbase, rk);

  /* stage h0 for this chain's 4 batches into h_buf[0] (own CTA only) */
  if (tid < 256){
    int b = tid >> 6, k4 = tid & 63;
    *(float4*)&h_buf[0][b][k4*4] =
        *(const float4*)(h0 + (size_t)(b0+b)*HID + k4*4);
  }

  /* epilogue ownership: tid<128 owns (b = tid>>5, jl = tid&31) */
  const int jl = tid & 31, ebi = (tid >> 5) & 3;
  const int eb = b0 + ebi, ej = j0 + jl;
  float c_reg = 0.f, xg0=0.f, xg1=0.f, xg2=0.f, xg3=0.f;
  if (tid < 128){
    c_reg = c0[eb*HID + ej];
    const float* xp = g_xg + (size_t)eb*GATE4 + ej;   /* t = 0 */
    xg0 = xp[0]; xg1 = xp[HID]; xg2 = xp[2*HID]; xg3 = xp[3*HID];
  }
  __syncthreads();

  for (int t=0; t<T_STEPS; ++t){
    const int buf = t & 1;

    /* ---- compute: loop over the chain's 4 batches; 8 rows per warp */
    #pragma unroll
    for (int b=0;b<4;b++){
      const float* hb = h_buf[buf][b] + lg*4;
      ulonglong2 hv0 = *(const ulonglong2*)(hb);
      ulonglong2 hv1 = *(const ulonglong2*)(hb+64);
      ulonglong2 hv2 = *(const ulonglong2*)(hb+128);
      ulonglong2 hv3 = *(const ulonglong2*)(hb+192);
      float v0, v1, v2, v3;
      #pragma unroll
      for (int r=0;r<4;r++){
        u64 s0 = fmul2(wr2[r][0].x, hv0.x);
        u64 s1 = fmul2(wr2[r][0].y, hv0.y);
        s0 = ffma2(wr2[r][1].x, hv1.x, s0);
        s1 = ffma2(wr2[r][1].y, hv1.y, s1);
        s0 = ffma2(wr2[r][2].x, hv2.x, s0);
        s1 = ffma2(wr2[r][2].y, hv2.y, s1);
        s0 = ffma2(wr2[r][3].x, hv3.x, s0);
        s1 = ffma2(wr2[r][3].y, hv3.y, s1);
        float v = hadd2(fadd2(s0, s1));
        if (r==0) v0=v; else if (r==1) v1=v; else if (r==2) v2=v; else v3=v;
      }
      /* reduce 4 rows over the 16 k-lanes: 8 SHFL (rh bit untouched) */
      v0 += __shfl_xor_sync(0xffffffffu, v0, 8);
      v1 += __shfl_xor_sync(0xffffffffu, v1, 8);
      v2 += __shfl_xor_sync(0xffffffffu, v2, 8);
      v3 += __shfl_xor_sync(0xffffffffu, v3, 8);
      float a = (lg & 8) ? v1 : v0;
      float bb = (lg & 8) ? v3 : v2;
      a  += __shfl_xor_sync(0xffffffffu, a, 4);
      bb += __shfl_xor_sync(0xffffffffu, bb, 4);
      float x = (lg & 4) ? bb : a;
      x += __shfl_xor_sync(0xffffffffu, x, 2);
      x += __shfl_xor_sync(0xffffffffu, x, 1);
      if ((lg & 3) == 0){
        const int rsel = ((lg>>3)&1) | (((lg>>2)&1)<<1);   /* 0,8,4,12 -> 0..3 */
        gates_sm[(wid*8 + rh*4 + rsel)*GST + b] = x;
      }
    }
    __syncthreads();

    /* ---- epilogue: activations, state update, DSMEM h broadcast */
    if (tid < 128){
      float pi = gates_sm[(0*32+jl)*GST + ebi] + xg0;
      float pf = gates_sm[(1*32+jl)*GST + ebi] + xg1;
      float pg = gates_sm[(2*32+jl)*GST + ebi] + xg2;
      float po = gates_sm[(3*32+jl)*GST + ebi] + xg3;
      float ii = fsigm(pi), ff = fsigm(pf), gg = ftanh(pg), oo = fsigm(po);
      c_reg = ff*c_reg + ii*gg;
      float hn = oo * ftanh(c_reg);

      /* broadcast h_new into every cluster CTA's h_buf[buf^1][ebi][ej] */
      const uint32_t doff = (uint32_t)(((buf^1)*1024 + ebi*256 + ej) * 4);
      #pragma unroll
      for (int rk=0; rk<8; rk++)
        st_cluster_f32(peer[rk] + doff, hn);

      out[(size_t)t*NG + eb*HID + ej] = hn;
      if (t == T_STEPS-1){
        out[(size_t)T_STEPS*NG + eb*HID + ej]      = hn;     /* h_T */
        out[(size_t)T_STEPS*NG + NG + eb*HID + ej] = c_reg;  /* c_T */
      } else {
        const float* xp = g_xg + ((size_t)(t+1)*BATCH + eb)*GATE4 + ej;
        xg0 = xp[0]; xg1 = xp[HID]; xg2 = xp[2*HID]; xg3 = xp[3*HID];
      }
    }

    /* ---- cluster barrier: release our DSMEM stores, acquire peers' */
    asm volatile("barrier.cluster.arrive.aligned;" ::: "memory");
    asm volatile("barrier.cluster.wait.aligned;"   ::: "memory");
  }
}

extern "C" void kernel_launch(void* const* d_in, const int* in_sizes, int n_in,
                              void* d_out, int out_size)
{
  (void)in_sizes; (void)n_in; (void)out_size;
  const float* input = (const float*)d_in[0];
  const float* h0    = (const float*)d_in[1];
  const float* c0    = (const float*)d_in[2];
  const float* W_ih  = (const float*)d_in[3];
  const float* W_hh  = (const float*)d_in[4];
  const float* b_ih  = (const float*)d_in[5];
  const float* b_hh  = (const float*)d_in[6];
  float* out = (float*)d_out;

  xgates_gemm<<<dim3(16,1024), 256>>>(input, W_ih, b_ih, b_hh);
  lstm_rec<<<128, REC_THREADS>>>(h0, c0, W_hh, out);
}

// round 6
// speedup vs baseline: 1.4512x; 1.4512x over previous
#include <cuda_runtime.h>
#include <math.h>
#include <stdint.h>

#define T_STEPS 2048
#define BATCH   64
#define HID     256
#define GATE4   1024
#define NG      (BATCH*HID)          /* 16384 */
#define REC_BLOCKS 128
#define REC_THREADS 512
#define CHAIN_BLOCKS 8               /* blocks per chain (one 4-batch group) */
#define GST     5                    /* gates_sm row stride (floats) */

typedef unsigned long long u64;

/* Scratch (device globals: no allocation allowed in kernel_launch) */
__device__ float g_xg[134217728];    /* [T][B][4H] precomputed input gates */
__device__ float g_h[2][NG];         /* double-buffered recurrent h */
__device__ unsigned g_bar16[512];    /* 16 chain barriers, 128B apart */
__device__ unsigned g_done;          /* end-of-kernel reset rendezvous */

/* ---- packed f32x2 helpers ---- */
__device__ __forceinline__ u64 ffma2(u64 a, u64 b, u64 c){
  u64 d; asm("fma.rn.f32x2 %0, %1, %2, %3;" : "=l"(d) : "l"(a), "l"(b), "l"(c));
  return d;
}
__device__ __forceinline__ u64 fmul2(u64 a, u64 b){
  u64 d; asm("mul.rn.f32x2 %0, %1, %2;" : "=l"(d) : "l"(a), "l"(b));
  return d;
}
__device__ __forceinline__ u64 fadd2(u64 a, u64 b){
  u64 d; asm("add.rn.f32x2 %0, %1, %2;" : "=l"(d) : "l"(a), "l"(b));
  return d;
}
__device__ __forceinline__ float hadd2(u64 a){
  unsigned lo, hi;
  asm("mov.b64 {%0, %1}, %2;" : "=r"(lo), "=r"(hi) : "l"(a));
  return __uint_as_float(lo) + __uint_as_float(hi);
}

__device__ __forceinline__ float fsigm(float x){
  return __fdividef(1.f, 1.f + __expf(-x));
}
__device__ __forceinline__ float ftanh(float x){
  return __fdividef(2.f, 1.f + __expf(-2.f*x)) - 1.f;
}
__device__ __forceinline__ unsigned ld_acq(const unsigned* p){
  unsigned v;
  asm volatile("ld.global.acquire.gpu.u32 %0, [%1];" : "=r"(v) : "l"(p) : "memory");
  return v;
}
__device__ __forceinline__ void red_rel_add(unsigned* p, unsigned v){
  asm volatile("red.release.gpu.global.add.u32 [%0], %1;" :: "l"(p), "r"(v) : "memory");
}

/* ---------------- Kernel A: x_gates = input @ W_ih^T + b_ih + b_hh ----------------
 * Round-3 plain-FFMA version (measured ~2.0ms, fp32 SIMT roofline). */
__global__ void __launch_bounds__(256, 2) xgates_gemm(
    const float* __restrict__ A, const float* __restrict__ W,
    const float* __restrict__ bih, const float* __restrict__ bhh)
{
  __shared__ float a_t[16][132];
  __shared__ float b_t[16][68];
  const int tid = threadIdx.x;
  const int bx = blockIdx.x, by = blockIdx.y;
  const int tx = tid & 15, ty = tid >> 4;

  float acc[8][4];
  #pragma unroll
  for (int m=0;m<8;m++)
    #pragma unroll
    for (int n=0;n<4;n++) acc[m][n]=0.f;

  const float* Ab = A + (size_t)by*128*256;
  const float* Wb = W + (size_t)bx*64*256;

  for (int kt=0; kt<16; ++kt){
    const int k0 = kt*16;
    #pragma unroll
    for (int r=0;r<2;r++){
      int idx = tid + r*256;
      int row = idx >> 2, kq = idx & 3;
      float4 v = *(const float4*)(Ab + (size_t)row*256 + k0 + kq*4);
      a_t[kq*4+0][row]=v.x; a_t[kq*4+1][row]=v.y;
      a_t[kq*4+2][row]=v.z; a_t[kq*4+3][row]=v.w;
    }
    {
      int n = tid >> 2, kq = tid & 3;
      float4 v = *(const float4*)(Wb + (size_t)n*256 + k0 + kq*4);
      b_t[kq*4+0][n]=v.x; b_t[kq*4+1][n]=v.y;
      b_t[kq*4+2][n]=v.z; b_t[kq*4+3][n]=v.w;
    }
    __syncthreads();
    #pragma unroll
    for (int k=0;k<16;k++){
      float af[8], bf[4];
      *(float4*)(af)   = *(const float4*)&a_t[k][ty*8];
      *(float4*)(af+4) = *(const float4*)&a_t[k][ty*8+4];
      *(float4*)(bf)   = *(const float4*)&b_t[k][tx*4];
      #pragma unroll
      for (int m=0;m<8;m++)
        #pragma unroll
        for (int n=0;n<4;n++)
          acc[m][n] += af[m]*bf[n];
    }
    __syncthreads();
  }

  const int gn = bx*64 + tx*4;
  const float bb0 = bih[gn+0]+bhh[gn+0];
  const float bb1 = bih[gn+1]+bhh[gn+1];
  const float bb2 = bih[gn+2]+bhh[gn+2];
  const float bb3 = bih[gn+3]+bhh[gn+3];
  #pragma unroll
  for (int m=0;m<8;m++){
    int gm = by*128 + ty*8 + m;
    float4 o = make_float4(acc[m][0]+bb0, acc[m][1]+bb1, acc[m][2]+bb2, acc[m][3]+bb3);
    *(float4*)(g_xg + (size_t)gm*GATE4 + gn) = o;
  }
}

/* ---------------- Kernel B: persistent recurrence ----------------
 * 16 independent chains x 8 blocks. Chain = one 4-batch group; block owns
 * 32 j x 4 gates = 128 gate-rows (W slice in regs, 64 floats/lane).
 * Handoff via L2: producers STG.cg h + release-red on the chain counter
 * (8 arrivals/step); consumers acquire-poll then stage 4KB of h.
 * Thread layout: warp wid owns rows wid*8..wid*8+7; lane = (lg: 16-way
 * k-split, rh: row-half). Per step/thread: 0.5 LDG.128 stage, 4 passes x
 * (4 LDS.128 + 32 FFMA2 + 8 SHFL), epilogue on tid<128, shadow stores. */
__global__ void __launch_bounds__(REC_THREADS, 1) lstm_rec(
    const float* __restrict__ h0, const float* __restrict__ c0,
    const float* __restrict__ W_hh, float* __restrict__ out)
{
  __shared__ float h_sm[4][256];         /* [local batch][k] : 4KB */
  __shared__ float gates_sm[128*GST];    /* [gate-row rl][b], rl = g*32+jl */

  const int tid  = threadIdx.x;
  const int blk  = blockIdx.x;
  const int bgid = blk & 15;             /* chain id (batch group) */
  const int jgid = blk >> 4;             /* j-group within chain   */
  const int b0   = bgid*4;
  const int j0   = jgid*32;
  unsigned* barp = &g_bar16[bgid*32];

  const int wid  = tid >> 5, lane = tid & 31;
  const int lg   = lane & 15, rh = lane >> 4;

  /* W_hh slice -> registers. rl in [0,128): gate = rl>>5, j = j0 + (rl&31). */
  ulonglong2 wr2[4][4];
  #pragma unroll
  for (int r=0;r<4;r++){
    const int rl = wid*8 + rh*4 + r;
    const int grow = (rl>>5)*HID + j0 + (rl&31);
    #pragma unroll
    for (int q=0;q<4;q++)
      wr2[r][q] = *(const ulonglong2*)(W_hh + (size_t)grow*HID + lg*4 + 64*q);
  }

  /* epilogue ownership: tid<128 owns (b = tid>>5, jl = tid&31) */
  const int jl = tid & 31, ebi = (tid >> 5) & 3;
  const int eb = b0 + ebi, ej = j0 + jl;
  float c_reg = 0.f, xg0=0.f, xg1=0.f, xg2=0.f, xg3=0.f;
  if (tid < 128){
    c_reg = c0[eb*HID + ej];
    const float* xp = g_xg + (size_t)eb*GATE4 + ej;   /* t = 0 */
    xg0 = xp[0]; xg1 = xp[HID]; xg2 = xp[2*HID]; xg3 = xp[3*HID];
  }

  for (int t=0; t<T_STEPS; ++t){
    /* ---- wait for previous step's h from this chain (acquire) */
    if (t){
      const unsigned target = (unsigned)t * CHAIN_BLOCKS;
      while (ld_acq(barp) < target) { }
    }

    /* ---- stage h: 4 batches x 256 = 4KB, tid<256 one float4 each (.cg) */
    if (tid < 256){
      const float4* hsrc = (const float4*)(((t==0) ? h0 : g_h[t & 1]) + b0*HID);
      const int b = tid >> 6, k4 = tid & 63;
      float4 v = __ldcg(hsrc + b*64 + k4);
      *(float4*)&h_sm[b][k4*4] = v;
    }
    __syncthreads();

    /* ---- compute: 4 batch passes; 8 rows per warp (rh picks 4), FFMA2 */
    #pragma unroll
    for (int b=0;b<4;b++){
      const float* hb = h_sm[b] + lg*4;
      ulonglong2 hv0 = *(const ulonglong2*)(hb);
      ulonglong2 hv1 = *(const ulonglong2*)(hb+64);
      ulonglong2 hv2 = *(const ulonglong2*)(hb+128);
      ulonglong2 hv3 = *(const ulonglong2*)(hb+192);
      float v0, v1, v2, v3;
      #pragma unroll
      for (int r=0;r<4;r++){
        u64 s0 = fmul2(wr2[r][0].x, hv0.x);
        u64 s1 = fmul2(wr2[r][0].y, hv0.y);
        s0 = ffma2(wr2[r][1].x, hv1.x, s0);
        s1 = ffma2(wr2[r][1].y, hv1.y, s1);
        s0 = ffma2(wr2[r][2].x, hv2.x, s0);
        s1 = ffma2(wr2[r][2].y, hv2.y, s1);
        s0 = ffma2(wr2[r][3].x, hv3.x, s0);
        s1 = ffma2(wr2[r][3].y, hv3.y, s1);
        float v = hadd2(fadd2(s0, s1));
        if (r==0) v0=v; else if (r==1) v1=v; else if (r==2) v2=v; else v3=v;
      }
      /* reduce 4 rows over the 16 k-lanes: 8 SHFL (rh bit untouched) */
      v0 += __shfl_xor_sync(0xffffffffu, v0, 8);
      v1 += __shfl_xor_sync(0xffffffffu, v1, 8);
      v2 += __shfl_xor_sync(0xffffffffu, v2, 8);
      v3 += __shfl_xor_sync(0xffffffffu, v3, 8);
      float a  = (lg & 8) ? v1 : v0;
      float bb = (lg & 8) ? v3 : v2;
      a  += __shfl_xor_sync(0xffffffffu, a, 4);
      bb += __shfl_xor_sync(0xffffffffu, bb, 4);
      float x = (lg & 4) ? bb : a;
      x += __shfl_xor_sync(0xffffffffu, x, 2);
      x += __shfl_xor_sync(0xffffffffu, x, 1);
      if ((lg & 3) == 0){
        const int rsel = ((lg>>3)&1) | (((lg>>2)&1)<<1);   /* 0,8,4,12 -> 0..3 */
        gates_sm[(wid*8 + rh*4 + rsel)*GST + b] = x;
      }
    }
    __syncthreads();

    /* ---- epilogue: activations + state update (c stays in a register) */
    float hn = 0.f;
    if (tid < 128){
      float pi = gates_sm[(0*32+jl)*GST + ebi] + xg0;
      float pf = gates_sm[(1*32+jl)*GST + ebi] + xg1;
      float pg = gates_sm[(2*32+jl)*GST + ebi] + xg2;
      float po = gates_sm[(3*32+jl)*GST + ebi] + xg3;
      float ii = fsigm(pi), ff = fsigm(pf), gg = ftanh(pg), oo = fsigm(po);
      c_reg = ff*c_reg + ii*gg;
      hn = oo * ftanh(c_reg);
      __stcg(&g_h[(t+1)&1][eb*HID + ej], hn);
    }
    __syncthreads();   /* h stores observed CTA-wide before tid0's release */

    /* ---- arrival (release), then out-stores + prefetch in its shadow */
    if (tid == 0) red_rel_add(barp, 1u);
    if (tid < 128){
      out[(size_t)t*NG + eb*HID + ej] = hn;
      if (t == T_STEPS-1){
        out[(size_t)T_STEPS*NG + eb*HID + ej]      = hn;     /* h_T */
        out[(size_t)T_STEPS*NG + NG + eb*HID + ej] = c_reg;  /* c_T */
      } else {
        const float* xp = g_xg + ((size_t)(t+1)*BATCH + eb)*GATE4 + ej;
        xg0 = xp[0]; xg1 = xp[HID]; xg2 = xp[2*HID]; xg3 = xp[3*HID];
      }
    }
  }

  /* reset counters for the next graph replay: last block to arrive does it */
  if (tid == 0){
    __threadfence();
    unsigned prev = atomicAdd(&g_done, 1u);
    if (prev == REC_BLOCKS-1){
      #pragma unroll
      for (int ch=0; ch<16; ch++) g_bar16[ch*32] = 0u;
      g_done = 0u;
      __threadfence();
    }
  }
}

extern "C" void kernel_launch(void* const* d_in, const int* in_sizes, int n_in,
                              void* d_out, int out_size)
{
  (void)in_sizes; (void)n_in; (void)out_size;
  const float* input = (const float*)d_in[0];
  const float* h0    = (const float*)d_in[1];
  const float* c0    = (const float*)d_in[2];
  const float* W_ih  = (const float*)d_in[3];
  const float* W_hh  = (const float*)d_in[4];
  const float* b_ih  = (const float*)d_in[5];
  const float* b_hh  = (const float*)d_in[6];
  float* out = (float*)d_out;

  xgates_gemm<<<dim3(16,1024), 256>>>(input, W_ih, b_ih, b_hh);
  lstm_rec<<<REC_BLOCKS, REC_THREADS>>>(h0, c0, W_hh, out);
}